// round 4
// baseline (speedup 1.0000x reference)
#include <cuda_runtime.h>
#include <cuda_bf16.h>
#include <cuda_fp16.h>
#include <cstdint>
#include <cstddef>

// ---------------------------------------------------------------------------
// GraphSAGE on sm_100 (base target):
//   CSR build (count -> multi-block scan -> fill)
//   3x [ segment-mean agg ; dual GEMM via mma.sync fp16 2-term ; +relu ]
//   final 128->64 linear
//
// Dual GEMM: X*Ws + XN*Wn == [X|XN] @ [Ws;Wn] -> one GEMM, K=256.
// Precision: A split x = hi_f16 + lo_f16 (exact to 2^-21); W stored as a
// single fp16 copy.  (hi + lo) @ W_f16 == x @ W_f16 -> the only error is
// fp16 rounding of W (~2e-4 RMS), well under the 1e-3 threshold, and the
// bench inputs are fixed -> deterministic rel_err.
// 2 MMA terms per k-step (was 3 with bf16 split) -> 33% less tensor work.
// ---------------------------------------------------------------------------

#define N_NODES 100000
#define N_EDGES 600000
#define F 128

// ---- scratch ---------------------------------------------------------------
__device__ float g_hbuf0[(size_t)N_NODES * F];
__device__ float g_hbuf1[(size_t)N_NODES * F];
__device__ float g_agg[(size_t)N_NODES * F];
__device__ float g_invdeg[N_NODES];
__device__ int   g_deg[N_NODES];
__device__ int   g_cursor[N_NODES];
__device__ int   g_csr_off[N_NODES + 1];
__device__ int   g_csr_src[N_EDGES];
__device__ int   g_part[128];
__device__ int   g_partoff[128];
// fp16 weights, [n][k]: layers 0..2: n 0..127, k 0..255 (k<128 self, else
// neigh); final: n 0..63, k 0..127.
#define W_TOTAL (3 * 128 * 256 + 64 * 128)
__device__ __half g_wh[W_TOTAL];

// ---- helpers ---------------------------------------------------------------
__device__ __forceinline__ uint32_t smem_u32(const void* p) {
    uint32_t a;
    asm("{ .reg .u64 t; cvta.to.shared.u64 t, %1; cvt.u32.u64 %0, t; }"
        : "=r"(a) : "l"(p));
    return a;
}
__device__ __forceinline__ void mma16816(float* c, const uint32_t* a,
                                         const uint32_t* b) {
    asm volatile(
        "mma.sync.aligned.m16n8k16.row.col.f32.f16.f16.f32 "
        "{%0,%1,%2,%3}, {%4,%5,%6,%7}, {%8,%9}, {%0,%1,%2,%3};"
        : "+f"(c[0]), "+f"(c[1]), "+f"(c[2]), "+f"(c[3])
        : "r"(a[0]), "r"(a[1]), "r"(a[2]), "r"(a[3]), "r"(b[0]), "r"(b[1]));
}
__device__ __forceinline__ void ldsm4(uint32_t* r, uint32_t addr) {
    asm volatile(
        "ldmatrix.sync.aligned.m8n8.x4.shared.b16 {%0,%1,%2,%3}, [%4];"
        : "=r"(r[0]), "=r"(r[1]), "=r"(r[2]), "=r"(r[3]) : "r"(addr));
}
#define SWZ(o) ((o) ^ (((o) >> 3) & 0x70))

// pack two floats as fp16x2 (low = a, high = b) + residuals
__device__ __forceinline__ uint32_t pk_h(float a, float b) {
    __half2 h = __floats2half2_rn(a, b);
    return *(uint32_t*)&h;
}

// ---- CSR build -------------------------------------------------------------
__global__ void init_kernel() {
    int i = blockIdx.x * blockDim.x + threadIdx.x;
    if (i < N_NODES) { g_deg[i] = 0; g_cursor[i] = 0; }
}
__global__ void count_kernel(const int* __restrict__ dst) {
    int e = blockIdx.x * blockDim.x + threadIdx.x;
    if (e < N_EDGES) atomicAdd(&g_deg[dst[e]], 1);
}
__global__ void blockscan_kernel() {
    __shared__ int ws[32];
    int tid = threadIdx.x, lane = tid & 31, w = tid >> 5;
    int i = blockIdx.x * 1024 + tid;
    int x = (i < N_NODES) ? g_deg[i] : 0;
    int inc = x;
    #pragma unroll
    for (int o = 1; o < 32; o <<= 1) {
        int v = __shfl_up_sync(0xFFFFFFFF, inc, o);
        if (lane >= o) inc += v;
    }
    if (lane == 31) ws[w] = inc;
    __syncthreads();
    if (w == 0) {
        int s = ws[lane];
        #pragma unroll
        for (int o = 1; o < 32; o <<= 1) {
            int v = __shfl_up_sync(0xFFFFFFFF, s, o);
            if (lane >= o) s += v;
        }
        ws[lane] = s;
    }
    __syncthreads();
    int base = (w == 0) ? 0 : ws[w - 1];
    if (i < N_NODES) g_csr_off[i] = base + inc - x;
    if (tid == 1023) g_part[blockIdx.x] = ws[31];
}
__global__ void partscan_kernel(int nparts) {
    __shared__ int ws[4];
    int tid = threadIdx.x, lane = tid & 31, w = tid >> 5;
    int x = (tid < nparts) ? g_part[tid] : 0;
    int inc = x;
    #pragma unroll
    for (int o = 1; o < 32; o <<= 1) {
        int v = __shfl_up_sync(0xFFFFFFFF, inc, o);
        if (lane >= o) inc += v;
    }
    if (lane == 31) ws[w] = inc;
    __syncthreads();
    if (tid == 0) {
        int s = 0;
        #pragma unroll
        for (int j = 0; j < 4; j++) { int t = ws[j]; ws[j] = s; s += t; }
    }
    __syncthreads();
    if (tid < nparts) g_partoff[tid] = ws[w] + inc - x;
}
__global__ void finalize_kernel() {
    int i = blockIdx.x * blockDim.x + threadIdx.x;
    if (i < N_NODES) {
        g_csr_off[i] += g_partoff[i >> 10];
        g_invdeg[i] = 1.0f / fmaxf((float)g_deg[i], 1.0f);
    }
    if (i == 0) g_csr_off[N_NODES] = N_EDGES;
}
__global__ void fill_kernel(const int* __restrict__ src,
                            const int* __restrict__ dst) {
    int e = blockIdx.x * blockDim.x + threadIdx.x;
    if (e < N_EDGES) {
        int d = dst[e];
        int pos = g_csr_off[d] + atomicAdd(&g_cursor[d], 1);
        g_csr_src[pos] = src[e];
    }
}

// ---- weight conversion to fp16 [n][k] --------------------------------------
__global__ void wconv_kernel(const float* w0s, const float* w0n,
                             const float* w1s, const float* w1n,
                             const float* w2s, const float* w2n,
                             const float* wo) {
    int idx = blockIdx.x * blockDim.x + threadIdx.x;
    if (idx >= W_TOTAL) return;
    float w;
    if (idx < 3 * 32768) {
        int l = idx >> 15, local = idx & 32767;
        int n = local >> 8, k = local & 255;
        const float* ws = (l == 0) ? w0s : (l == 1) ? w1s : w2s;
        const float* wn = (l == 0) ? w0n : (l == 1) ? w1n : w2n;
        w = (k < 128) ? ws[k * 128 + n] : wn[(k - 128) * 128 + n];
    } else {
        int local = idx - 3 * 32768;
        int n = local >> 7, k = local & 127;
        w = wo[k * 64 + n];
    }
    g_wh[idx] = __float2half_rn(w);
}

// ---- aggregation: warp per node, segment mean ------------------------------
__global__ void agg_kernel(const float* __restrict__ X) {
    int w = (blockIdx.x * blockDim.x + threadIdx.x) >> 5;
    int lane = threadIdx.x & 31;
    if (w >= N_NODES) return;
    int beg = g_csr_off[w], end = g_csr_off[w + 1];
    float4 acc = make_float4(0.f, 0.f, 0.f, 0.f);
    for (int e = beg; e < end; e++) {
        int s = g_csr_src[e];
        float4 v = *(const float4*)&X[(size_t)s * F + lane * 4];
        acc.x += v.x; acc.y += v.y; acc.z += v.z; acc.w += v.w;
    }
    float inv = g_invdeg[w];
    *(float4*)&g_agg[(size_t)w * F + lane * 4] =
        make_float4(acc.x * inv, acc.y * inv, acc.z * inv, acc.w * inv);
}

// ---- mma.sync fp16 2-term GEMM --------------------------------------------
// Y[128b x N_OUT] = [X | XN] @ W_f16 + bias (+relu), A split hi+lo fp16.
template <int N_OUT, bool DUAL, bool RELU>
__global__ void __launch_bounds__(256) sage_mma(
    const float* __restrict__ X, const float* __restrict__ XN,
    const __half* __restrict__ Wh,
    const float* __restrict__ bsv, const float* __restrict__ bnv,
    float* __restrict__ Y) {
    constexpr int KTOT = DUAL ? 256 : 128;
    constexpr int NCH = KTOT / 64;            // K chunks of 64
    constexpr int NWN = N_OUT / 32;           // warps along N (4 or 2)
    constexpr int MI = 128 / (8 / NWN) / 16;  // m16 frags per warp (4 or 2)
    constexpr int OFF_B = 65536;              // after 2 A double-buffers
    constexpr int BMAT = NCH * N_OUT * 128;   // bytes for the weight mat
    constexpr int OFF_BIAS = OFF_B + BMAT;

    extern __shared__ char smc[];
    const uint32_t sb = smem_u32(smc);
    const int tid = threadIdx.x, wid = tid >> 5, lane = tid & 31;
    const int node0 = blockIdx.x * 128;
    float* sB = (float*)(smc + OFF_BIAS);
    if (tid < N_OUT) sB[tid] = bsv[tid] + (DUAL ? bnv[tid] : 0.0f);

    // B: smem-resident fp16 weights, SW128-swizzled 128B rows per k-chunk
    for (int idx = tid; idx < N_OUT * KTOT / 8; idx += 256) {
        int n = idx / (KTOT / 8);
        int k = (idx % (KTOT / 8)) * 8;
        uint4 v = *(const uint4*)(Wh + n * KTOT + k);
        uint32_t off = (uint32_t)(n * 128 + (k & 63) * 2);
        off = SWZ(off);
        *(uint4*)(smc + OFF_B + (k >> 6) * (N_OUT * 128) + off) = v;
    }

    // A producer: each thread owns half a row (32 floats) of the 128-node tile
    float4 st[8];
    const int arow = tid >> 1;
    const int acolb = (tid & 1) * 32;
    const int pnode = node0 + arow;
    auto do_ldg = [&](int c) {
        const float* src = (DUAL && c >= 2) ? (XN + (c - 2) * 64) : (X + c * 64);
        if (pnode < N_NODES) {
            const float4* p = (const float4*)(src + (size_t)pnode * F + acolb);
            #pragma unroll
            for (int j = 0; j < 8; j++) st[j] = p[j];
        } else {
            #pragma unroll
            for (int j = 0; j < 8; j++) st[j] = make_float4(0.f, 0.f, 0.f, 0.f);
        }
    };
    auto do_sts = [&](int b) {
        char* dhi = smc + b * 32768;
        char* dlo = dhi + 16384;
        #pragma unroll
        for (int j = 0; j < 4; j++) {
            float4 v0 = st[2 * j], v1 = st[2 * j + 1];
            uint4 H, L;
            H.x = pk_h(v0.x, v0.y); H.y = pk_h(v0.z, v0.w);
            H.z = pk_h(v1.x, v1.y); H.w = pk_h(v1.z, v1.w);
            __half2 h0 = *(__half2*)&H.x, h1 = *(__half2*)&H.y;
            __half2 h2 = *(__half2*)&H.z, h3 = *(__half2*)&H.w;
            L.x = pk_h(v0.x - __half2float(h0.x), v0.y - __half2float(h0.y));
            L.y = pk_h(v0.z - __half2float(h1.x), v0.w - __half2float(h1.y));
            L.z = pk_h(v1.x - __half2float(h2.x), v1.y - __half2float(h2.y));
            L.w = pk_h(v1.z - __half2float(h3.x), v1.w - __half2float(h3.y));
            uint32_t off = (uint32_t)(arow * 128 + (acolb + 8 * j) * 2);
            off = SWZ(off);
            *(uint4*)(dhi + off) = H;
            *(uint4*)(dlo + off) = L;
        }
    };

    // lane-invariant ldmatrix bases
    const int wn = (wid % NWN) * 32;
    const int wm = (wid / NWN) * (MI * 16);
    const int ar = wm + (lane & 15);
    const uint32_t a_base = (uint32_t)(ar * 128 + (lane >> 4) * 16);
    const uint32_t a_mask = (uint32_t)((ar & 7) << 4);
    const int br = wn + (lane & 7) + ((lane >> 4) << 3);
    const uint32_t b_base = (uint32_t)(br * 128 + ((lane >> 3) & 1) * 16);
    const uint32_t b_mask = (uint32_t)((br & 7) << 4);

    float acc[MI][4][4];
    #pragma unroll
    for (int mi = 0; mi < MI; mi++)
        #pragma unroll
        for (int ni = 0; ni < 4; ni++)
            #pragma unroll
            for (int q = 0; q < 4; q++) acc[mi][ni][q] = 0.f;

    do_ldg(0);
    do_sts(0);
    __syncthreads();

    #pragma unroll 1
    for (int c = 0; c < NCH; c++) {
        if (c + 1 < NCH) do_ldg(c + 1);
        const uint32_t ahi = sb + (c & 1) * 32768;
        const uint32_t alo = ahi + 16384;
        const uint32_t bb = sb + OFF_B + c * (N_OUT * 128);
        #pragma unroll
        for (int ks = 0; ks < 4; ks++) {
            uint32_t ah[MI][4], al[MI][4], bh[4][2];
            uint32_t ka = (a_base + ks * 32) ^ a_mask;
            #pragma unroll
            for (int mi = 0; mi < MI; mi++) {
                ldsm4(ah[mi], ahi + ka + mi * 2048);
                ldsm4(al[mi], alo + ka + mi * 2048);
            }
            uint32_t kb = (b_base + ks * 32) ^ b_mask;
            ldsm4(&bh[0][0], bb + kb);
            ldsm4(&bh[2][0], bb + kb + 2048);
            #pragma unroll
            for (int mi = 0; mi < MI; mi++)
                #pragma unroll
                for (int ni = 0; ni < 4; ni++)
                    mma16816(acc[mi][ni], ah[mi], bh[ni]);
            #pragma unroll
            for (int mi = 0; mi < MI; mi++)
                #pragma unroll
                for (int ni = 0; ni < 4; ni++)
                    mma16816(acc[mi][ni], al[mi], bh[ni]);
        }
        if (c + 1 < NCH) {
            do_sts((c + 1) & 1);
            __syncthreads();
        }
    }

    // epilogue
    const int erow = wm + (lane >> 2);
    const int ecol = wn + (lane & 3) * 2;
    #pragma unroll
    for (int mi = 0; mi < MI; mi++) {
        #pragma unroll
        for (int h = 0; h < 2; h++) {
            int gr = node0 + erow + mi * 16 + h * 8;
            if (gr >= N_NODES) continue;
            float* yp = Y + (size_t)gr * N_OUT;
            #pragma unroll
            for (int ni = 0; ni < 4; ni++) {
                float2 o;
                o.x = acc[mi][ni][2 * h] + sB[ecol + ni * 8];
                o.y = acc[mi][ni][2 * h + 1] + sB[ecol + ni * 8 + 1];
                if (RELU) { o.x = fmaxf(o.x, 0.f); o.y = fmaxf(o.y, 0.f); }
                *(float2*)(yp + ecol + ni * 8) = o;
            }
        }
    }
}

// ---------------------------------------------------------------------------
extern "C" void kernel_launch(void* const* d_in, const int* in_sizes, int n_in,
                              void* d_out, int out_size) {
    const float* feats = (const float*)d_in[0];
    const int* src = (const int*)d_in[1];
    const int* dst = (const int*)d_in[2];
    const float* Ws[3] = {(const float*)d_in[3], (const float*)d_in[7],
                          (const float*)d_in[11]};
    const float* bs[3] = {(const float*)d_in[4], (const float*)d_in[8],
                          (const float*)d_in[12]};
    const float* Wn[3] = {(const float*)d_in[5], (const float*)d_in[9],
                          (const float*)d_in[13]};
    const float* bn[3] = {(const float*)d_in[6], (const float*)d_in[10],
                          (const float*)d_in[14]};
    const float* Wout = (const float*)d_in[15];
    const float* bout = (const float*)d_in[16];

    float *h0, *h1, *agg;
    __half* wh;
    cudaGetSymbolAddress((void**)&h0, g_hbuf0);
    cudaGetSymbolAddress((void**)&h1, g_hbuf1);
    cudaGetSymbolAddress((void**)&agg, g_agg);
    cudaGetSymbolAddress((void**)&wh, g_wh);

    // smem: 64KB A bufs + BMAT weights + bias
    const int SMEM_DUAL = 65536 + 4 * 128 * 128 + 512;   // 131,584
    const int SMEM_FIN  = 65536 + 2 * 64 * 128 + 256;    //  82,176

    auto kRelu = sage_mma<128, true, true>;
    auto kNoRelu = sage_mma<128, true, false>;
    auto kFinal = sage_mma<64, false, false>;
    cudaFuncSetAttribute((const void*)kRelu,
                         cudaFuncAttributeMaxDynamicSharedMemorySize, SMEM_DUAL);
    cudaFuncSetAttribute((const void*)kNoRelu,
                         cudaFuncAttributeMaxDynamicSharedMemorySize, SMEM_DUAL);
    cudaFuncSetAttribute((const void*)kFinal,
                         cudaFuncAttributeMaxDynamicSharedMemorySize, SMEM_FIN);

    // CSR build
    const int NPART = (N_NODES + 1023) / 1024;  // 98
    init_kernel<<<(N_NODES + 255) / 256, 256>>>();
    count_kernel<<<(N_EDGES + 255) / 256, 256>>>(dst);
    blockscan_kernel<<<NPART, 1024>>>();
    partscan_kernel<<<1, 128>>>(NPART);
    finalize_kernel<<<(N_NODES + 255) / 256, 256>>>();
    fill_kernel<<<(N_EDGES + 255) / 256, 256>>>(src, dst);

    // weight conversion
    wconv_kernel<<<(W_TOTAL + 255) / 256, 256>>>(Ws[0], Wn[0], Ws[1], Wn[1],
                                                 Ws[2], Wn[2], Wout);

    const int AGG_BLOCKS = (N_NODES * 32 + 255) / 256;
    const int GB = (N_NODES + 127) / 128;  // 782

    agg_kernel<<<AGG_BLOCKS, 256>>>(feats);
    kRelu<<<GB, 256, SMEM_DUAL>>>(feats, agg, wh, bs[0], bn[0], h0);
    agg_kernel<<<AGG_BLOCKS, 256>>>(h0);
    kRelu<<<GB, 256, SMEM_DUAL>>>(h0, agg, wh + 32768, bs[1], bn[1], h1);
    agg_kernel<<<AGG_BLOCKS, 256>>>(h1);
    kNoRelu<<<GB, 256, SMEM_DUAL>>>(h1, agg, wh + 65536, bs[2], bn[2], h0);
    kFinal<<<GB, 256, SMEM_FIN>>>(h0, nullptr, wh + 98304, bout, nullptr,
                                  (float*)d_out);
}